// round 16
// baseline (speedup 1.0000x reference)
#include <cuda_runtime.h>
#include <cuda_bf16.h>

// Problem: B=2, L=2048, D=1024, H=16, DH=64
// Output buffer: [output (B,L,D) = 4,194,304 f32][attn (B,H,L,L) = 134,217,728 f32]

#define B_SZ   2
#define L_SZ   2048
#define D_SZ   1024
#define H_SZ   16
#define DH_SZ  64

static constexpr size_t OUT_ELEMS  = (size_t)B_SZ * L_SZ * D_SZ;        // 4194304
static constexpr size_t ATTN_ELEMS = (size_t)B_SZ * H_SZ * L_SZ * L_SZ; // 134217728
static constexpr size_t QKV_ELEMS  = (size_t)B_SZ * H_SZ * L_SZ * DH_SZ;// 4194304

// Scratch (allocation-free rule: __device__ globals)
__device__ __align__(16) float g_q[QKV_ELEMS];
__device__ __align__(16) float g_k[QKV_ELEMS];
__device__ __align__(16) float g_v[QKV_ELEMS];
__device__ __align__(16) float g_ctx[OUT_ELEMS];                      // ctx concat (B,L,D)
__device__ __align__(16) float2 g_stats[(size_t)B_SZ * H_SZ * L_SZ];  // {rowmax, 1/Z}
// Fallback attn scratch in case out_size only covers `output`
__device__ __align__(16) float g_attn_fb[ATTN_ELEMS];

__device__ __forceinline__ unsigned f2tf(float f) {
    unsigned u;
    asm("cvt.rna.tf32.f32 %0, %1;" : "=r"(u) : "f"(f));
    return u;
}

__device__ __forceinline__ void mma8(float c[4], const unsigned a[4], const unsigned b[2]) {
    asm volatile(
        "mma.sync.aligned.m16n8k8.row.col.f32.tf32.tf32.f32 "
        "{%0,%1,%2,%3}, {%4,%5,%6,%7}, {%8,%9}, {%0,%1,%2,%3};"
        : "+f"(c[0]), "+f"(c[1]), "+f"(c[2]), "+f"(c[3])
        : "r"(a[0]), "r"(a[1]), "r"(a[2]), "r"(a[3]), "r"(b[0]), "r"(b[1]));
}

// merge two (max, sumexp) pairs
__device__ __forceinline__ void mz_merge(float& m, float& z, float om, float oz) {
    float mn = fmaxf(m, om);
    z = z * __expf(m - mn) + oz * __expf(om - mn);
    m = mn;
}

// ============================================================================
// NT GEMM: C[M=4096, N=1024] = A[4096,1024] * W[1024,1024]^T, TF32 mma.
// 512 threads, 16 warps (4m x 4n), warp tile 32x32, BM=BN=128, BK=32.
// 2-stage smem double buffer with register prefetch.
// __launch_bounds__(512, 2): cap regs at 64 so TWO CTAs fit per SM (occ 50%).
// mode < 0: md = blockIdx.z in {0,1,2}: A = x, scatter into g_q/g_k/g_v (B,H,L,DH).
// mode == 3: A = g_ctx (concat), plain row-major write to dst.
// ============================================================================
static constexpr int PROJ_SMEM = (2 * 128 * 36 * 2) * 4;  // 73728 B (x2 CTAs = 147456)

__global__ void __launch_bounds__(512, 2) proj_kernel(
    const float* __restrict__ Ain, const float* __restrict__ W0,
    const float* __restrict__ W1, const float* __restrict__ W2,
    float* __restrict__ dst, int mode)
{
    extern __shared__ unsigned sh[];
    unsigned (*As)[128][36] = (unsigned(*)[128][36])sh;
    unsigned (*Ws)[128][36] = (unsigned(*)[128][36])(sh + 2 * 128 * 36);

    const int md = (mode < 0) ? (int)blockIdx.z : mode;
    const float* W = (md == 1) ? W1 : (md == 2) ? W2 : W0;
    const float* A = (md == 3) ? (const float*)g_ctx : Ain;

    const int tid  = threadIdx.x;
    const int wid  = tid >> 5;
    const int lane = tid & 31;
    const int g = lane >> 2, t = lane & 3;
    const int warp_m = wid & 3, warp_n = wid >> 2;
    const int m0 = blockIdx.y * 128;
    const int n0 = blockIdx.x * 128;

    const int lr = tid >> 3;          // 0..63 (row within stage, +64 for i=1)
    const int lc = (tid & 7) << 2;    // 0..28

    float acc[2][4][4];
#pragma unroll
    for (int i = 0; i < 2; i++)
#pragma unroll
        for (int j = 0; j < 4; j++)
#pragma unroll
            for (int c = 0; c < 4; c++) acc[i][j][c] = 0.f;

    // preload stage 0
#pragma unroll
    for (int i = 0; i < 2; i++) {
        int r = lr + i * 64;
        float4 fa = *(const float4*)(A + (size_t)(m0 + r) * 1024 + lc);
        float4 fw = *(const float4*)(W + (size_t)(n0 + r) * 1024 + lc);
        *(uint4*)&As[0][r][lc] = make_uint4(f2tf(fa.x), f2tf(fa.y), f2tf(fa.z), f2tf(fa.w));
        *(uint4*)&Ws[0][r][lc] = make_uint4(f2tf(fw.x), f2tf(fw.y), f2tf(fw.z), f2tf(fw.w));
    }
    __syncthreads();

    int st = 0;
    for (int k0 = 0; k0 < 1024; k0 += 32) {
        const bool nxt = (k0 + 32) < 1024;
        float4 pa[2], pw[2];
        if (nxt) {
#pragma unroll
            for (int i = 0; i < 2; i++) {
                int r = lr + i * 64;
                pa[i] = *(const float4*)(A + (size_t)(m0 + r) * 1024 + k0 + 32 + lc);
                pw[i] = *(const float4*)(W + (size_t)(n0 + r) * 1024 + k0 + 32 + lc);
            }
        }
#pragma unroll
        for (int kk = 0; kk < 32; kk += 8) {
            unsigned af[2][4], bf[4][2];
#pragma unroll
            for (int i = 0; i < 2; i++) {
                int rb = warp_m * 32 + i * 16 + g;
                af[i][0] = As[st][rb][kk + t];
                af[i][1] = As[st][rb + 8][kk + t];
                af[i][2] = As[st][rb][kk + t + 4];
                af[i][3] = As[st][rb + 8][kk + t + 4];
            }
#pragma unroll
            for (int j = 0; j < 4; j++) {
                int cb = warp_n * 32 + j * 8 + g;
                bf[j][0] = Ws[st][cb][kk + t];
                bf[j][1] = Ws[st][cb][kk + t + 4];
            }
#pragma unroll
            for (int i = 0; i < 2; i++)
#pragma unroll
                for (int j = 0; j < 4; j++)
                    mma8(acc[i][j], af[i], bf[j]);
        }
        if (nxt) {
#pragma unroll
            for (int i = 0; i < 2; i++) {
                int r = lr + i * 64;
                *(uint4*)&As[st ^ 1][r][lc] = make_uint4(f2tf(pa[i].x), f2tf(pa[i].y), f2tf(pa[i].z), f2tf(pa[i].w));
                *(uint4*)&Ws[st ^ 1][r][lc] = make_uint4(f2tf(pw[i].x), f2tf(pw[i].y), f2tf(pw[i].z), f2tf(pw[i].w));
            }
        }
        __syncthreads();
        st ^= 1;
    }

    // Epilogue
#pragma unroll
    for (int i = 0; i < 2; i++) {
#pragma unroll
        for (int j = 0; j < 4; j++) {
            int r0 = m0 + warp_m * 32 + i * 16 + g;
            int c0 = n0 + warp_n * 32 + j * 8 + 2 * t;
            float2 lo = make_float2(acc[i][j][0], acc[i][j][1]);
            float2 hi = make_float2(acc[i][j][2], acc[i][j][3]);
            if (md == 3) {
                *(float2*)(dst + (size_t)r0 * 1024 + c0) = lo;
                *(float2*)(dst + (size_t)(r0 + 8) * 1024 + c0) = hi;
            } else {
                float* qkv = (md == 0) ? g_q : (md == 1) ? g_k : g_v;
                size_t i0 = ((size_t)((r0 >> 11) * H_SZ + (c0 >> 6)) * L_SZ + (r0 & 2047)) * DH_SZ + (c0 & 63);
                *(float2*)(qkv + i0) = lo;
                int r1 = r0 + 8;
                size_t i1 = ((size_t)((r1 >> 11) * H_SZ + (c0 >> 6)) * L_SZ + (r1 & 2047)) * DH_SZ + (c0 & 63);
                *(float2*)(qkv + i1) = hi;
            }
        }
    }
}

// ============================================================================
// Stats (flash pass-1): per (b,h, row-block 128), recompute S = Q K^T * 0.125
// streaming K in 128-col tiles; produce per-row (max M, 1/Z), Z = sum exp(s-M).
// SINGLE-buffer K (register prefetch across the mma) -> smem 72KB,
// __launch_bounds__(512, 2) -> 2 CTAs/SM; extra barrier hidden by co-resident CTA.
// Same mma fragment order as the fused attn kernel -> identical s values.
// ============================================================================
static constexpr int STAT_SMEM = (128 * 68 + 128 * 68 + 4 * 128 * 2) * 4; // 73728 B

__global__ void __launch_bounds__(512, 2) stats_kernel()
{
    extern __shared__ unsigned sh[];
    unsigned (*Qs)[68]       = (unsigned(*)[68])sh;
    unsigned (*Ks)[68]       = (unsigned(*)[68])(sh + 128 * 68);
    float    (*red)[128][2]  = (float(*)[128][2])(sh + 2 * 128 * 68);

    const int tid  = threadIdx.x;
    const int lane = tid & 31;
    const int wid  = tid >> 5;
    const int g = lane >> 2, t = lane & 3;
    const int warp_m = wid & 3, warp_n = wid >> 2;
    const int m0 = blockIdx.x * 128;
    const int bh = blockIdx.y;

    const float* Qb = g_q + (size_t)bh * L_SZ * DH_SZ;
    const float* Kb = g_k + (size_t)bh * L_SZ * DH_SZ;

    const int lr = tid >> 4;          // 0..31 (+32 per i), 16 float4 per 64-wide row
    const int lc = (tid & 15) << 2;

#pragma unroll
    for (int i = 0; i < 4; i++) {
        int r = lr + i * 32;
        float4 fq = *(const float4*)(Qb + (size_t)(m0 + r) * DH_SZ + lc);
        *(uint4*)&Qs[r][lc] = make_uint4(f2tf(fq.x), f2tf(fq.y), f2tf(fq.z), f2tf(fq.w));
        float4 fk = *(const float4*)(Kb + (size_t)r * DH_SZ + lc);
        *(uint4*)&Ks[r][lc] = make_uint4(f2tf(fk.x), f2tf(fk.y), f2tf(fk.z), f2tf(fk.w));
    }
    __syncthreads();

    float m_[4] = {-1e30f, -1e30f, -1e30f, -1e30f};
    float z_[4] = {0.f, 0.f, 0.f, 0.f};

    for (int n0 = 0; n0 < L_SZ; n0 += 128) {
        const bool nxt = (n0 + 128) < L_SZ;
        float4 pk[4];
        if (nxt) {
#pragma unroll
            for (int i = 0; i < 4; i++) {
                int r = lr + i * 32;
                pk[i] = *(const float4*)(Kb + (size_t)(n0 + 128 + r) * DH_SZ + lc);
            }
        }
        float acc[2][4][4];
#pragma unroll
        for (int i = 0; i < 2; i++)
#pragma unroll
            for (int j = 0; j < 4; j++)
#pragma unroll
                for (int c = 0; c < 4; c++) acc[i][j][c] = 0.f;

#pragma unroll
        for (int kk = 0; kk < 64; kk += 8) {
            unsigned af[2][4], bf[4][2];
#pragma unroll
            for (int i = 0; i < 2; i++) {
                int rb = warp_m * 32 + i * 16 + g;
                af[i][0] = Qs[rb][kk + t];
                af[i][1] = Qs[rb + 8][kk + t];
                af[i][2] = Qs[rb][kk + t + 4];
                af[i][3] = Qs[rb + 8][kk + t + 4];
            }
#pragma unroll
            for (int j = 0; j < 4; j++) {
                int cb = warp_n * 32 + j * 8 + g;
                bf[j][0] = Ks[cb][kk + t];
                bf[j][1] = Ks[cb][kk + t + 4];
            }
#pragma unroll
            for (int i = 0; i < 2; i++)
#pragma unroll
                for (int j = 0; j < 4; j++)
                    mma8(acc[i][j], af[i], bf[j]);
        }
        // online (m,z) update from this tile (register-only)
#pragma unroll
        for (int i = 0; i < 2; i++) {
#pragma unroll
            for (int half = 0; half < 2; half++) {
                int ri = i * 2 + half;
                float v[8];
#pragma unroll
                for (int j = 0; j < 4; j++) {
                    v[2 * j]     = acc[i][j][half * 2]     * 0.125f;
                    v[2 * j + 1] = acc[i][j][half * 2 + 1] * 0.125f;
                }
                float tm = v[0];
#pragma unroll
                for (int k = 1; k < 8; k++) tm = fmaxf(tm, v[k]);
                float mn = fmaxf(m_[ri], tm);
                float zs = 0.f;
#pragma unroll
                for (int k = 0; k < 8; k++) zs += __expf(v[k] - mn);
                z_[ri] = z_[ri] * __expf(m_[ri] - mn) + zs;
                m_[ri] = mn;
            }
        }
        __syncthreads();          // everyone done reading Ks
        if (nxt) {
#pragma unroll
            for (int i = 0; i < 4; i++) {
                int r = lr + i * 32;
                *(uint4*)&Ks[r][lc] = make_uint4(f2tf(pk[i].x), f2tf(pk[i].y), f2tf(pk[i].z), f2tf(pk[i].w));
            }
            __syncthreads();      // Ks refilled
        }
    }

#pragma unroll
    for (int ri = 0; ri < 4; ri++) {
#pragma unroll
        for (int o = 1; o < 4; o <<= 1) {
            float om = __shfl_xor_sync(0xffffffffu, m_[ri], o);
            float oz = __shfl_xor_sync(0xffffffffu, z_[ri], o);
            mz_merge(m_[ri], z_[ri], om, oz);
        }
    }
    if (t == 0) {
#pragma unroll
        for (int i = 0; i < 2; i++) {
            int rl = warp_m * 32 + i * 16 + g;
            red[warp_n][rl][0]     = m_[i * 2];
            red[warp_n][rl][1]     = z_[i * 2];
            red[warp_n][rl + 8][0] = m_[i * 2 + 1];
            red[warp_n][rl + 8][1] = z_[i * 2 + 1];
        }
    }
    __syncthreads();
    if (tid < 128) {
        float M = red[0][tid][0], Z = red[0][tid][1];
#pragma unroll
        for (int w = 1; w < 4; w++) mz_merge(M, Z, red[w][tid][0], red[w][tid][1]);
        g_stats[(size_t)bh * L_SZ + m0 + tid] = make_float2(M, 1.0f / Z);
    }
}

// ============================================================================
// Fused attention: per (bh, 128-row Q block), loop over 16 K/V tiles of 128:
//   S = Q K^T * 0.125; P = exp(S - M) * invZ (stats precomputed);
//   write fp32 P to attn (streaming store, never re-read);
//   store tf32 P to smem; ctx += P @ V from smem.
// Q resident in smem all kernel. K double-buffered; V prefetched via regs.
// smem = 208896 B -> 1 CTA/SM, 16 warps.
// ============================================================================
static constexpr int ATTN_SMEM = (128 * 68 + 2 * 128 * 68 + 128 * 72 + 128 * 132) * 4; // 208896

__global__ void __launch_bounds__(512) attn_kernel(float* __restrict__ out, int fb)
{
    extern __shared__ unsigned sh[];
    unsigned (*Qs)[68]       = (unsigned(*)[68])sh;                         // 8704
    unsigned (*Ks)[128][68]  = (unsigned(*)[128][68])(sh + 8704);           // 17408
    unsigned (*Vs)[72]       = (unsigned(*)[72])(sh + 26112);               // 9216
    unsigned (*Ps)[132]      = (unsigned(*)[132])(sh + 35328);              // 16896

    float* attn = fb ? g_attn_fb : out + OUT_ELEMS;
    const int bh = blockIdx.y;
    const int m0 = blockIdx.x * 128;
    const int b  = bh >> 4;
    const int h  = bh & 15;

    const int tid  = threadIdx.x;
    const int lane = tid & 31;
    const int wid  = tid >> 5;
    const int g = lane >> 2, t = lane & 3;
    const int warp_m = wid & 3, warp_n = wid >> 2;

    const float* Qb = g_q + (size_t)bh * L_SZ * DH_SZ;
    const float* Kb = g_k + (size_t)bh * L_SZ * DH_SZ;
    const float* Vb = g_v + (size_t)bh * L_SZ * DH_SZ;
    float* Sb = attn + (size_t)bh * L_SZ * L_SZ;

    const int lr = tid >> 4;          // 0..31 (+32*i), 16 float4 per 64-wide row
    const int lc = (tid & 15) << 2;

    // per-thread softmax stats for the 4 rows this thread's fragments touch
    float rowM[2][2], rowI[2][2];
#pragma unroll
    for (int i = 0; i < 2; i++) {
        int rl = warp_m * 32 + i * 16 + g;
        float2 s0 = g_stats[(size_t)bh * L_SZ + m0 + rl];
        float2 s1 = g_stats[(size_t)bh * L_SZ + m0 + rl + 8];
        rowM[i][0] = s0.x; rowI[i][0] = s0.y;
        rowM[i][1] = s1.x; rowI[i][1] = s1.y;
    }

    // ctx accumulators: warp tile 32(m) x 16(dh)
    float ctx[2][2][4];
#pragma unroll
    for (int i = 0; i < 2; i++)
#pragma unroll
        for (int j = 0; j < 2; j++)
#pragma unroll
            for (int c = 0; c < 4; c++) ctx[i][j][c] = 0.f;

    // preload Q (resident), K tile 0, V tile 0
#pragma unroll
    for (int i = 0; i < 4; i++) {
        int r = lr + i * 32;
        float4 fq = *(const float4*)(Qb + (size_t)(m0 + r) * DH_SZ + lc);
        *(uint4*)&Qs[r][lc] = make_uint4(f2tf(fq.x), f2tf(fq.y), f2tf(fq.z), f2tf(fq.w));
        float4 fk = *(const float4*)(Kb + (size_t)r * DH_SZ + lc);
        *(uint4*)&Ks[0][r][lc] = make_uint4(f2tf(fk.x), f2tf(fk.y), f2tf(fk.z), f2tf(fk.w));
        float4 fv = *(const float4*)(Vb + (size_t)r * DH_SZ + lc);
        *(uint4*)&Vs[r][lc] = make_uint4(f2tf(fv.x), f2tf(fv.y), f2tf(fv.z), f2tf(fv.w));
    }
    __syncthreads();

    int st = 0;
    for (int it = 0; it < 16; it++) {
        const bool nxt = it < 15;
        // prefetch next K/V tiles into registers (hidden under S mma)
        float4 kreg[4], vreg[4];
        if (nxt) {
            const float* Kn = Kb + (size_t)(it + 1) * 128 * DH_SZ;
            const float* Vn = Vb + (size_t)(it + 1) * 128 * DH_SZ;
#pragma unroll
            for (int i = 0; i < 4; i++) {
                int r = lr + i * 32;
                kreg[i] = *(const float4*)(Kn + (size_t)r * DH_SZ + lc);
                vreg[i] = *(const float4*)(Vn + (size_t)r * DH_SZ + lc);
            }
        }

        // ---- S = Q K^T ----
        float pacc[2][4][4];
#pragma unroll
        for (int i = 0; i < 2; i++)
#pragma unroll
            for (int j = 0; j < 4; j++)
#pragma unroll
                for (int c = 0; c < 4; c++) pacc[i][j][c] = 0.f;

#pragma unroll
        for (int kk = 0; kk < 64; kk += 8) {
            unsigned af[2][4], bf[4][2];
#pragma unroll
            for (int i = 0; i < 2; i++) {
                int rb = warp_m * 32 + i * 16 + g;
                af[i][0] = Qs[rb][kk + t];
                af[i][1] = Qs[rb + 8][kk + t];
                af[i][2] = Qs[rb][kk + t + 4];
                af[i][3] = Qs[rb + 8][kk + t + 4];
            }
#pragma unroll
            for (int j = 0; j < 4; j++) {
                int cb = warp_n * 32 + j * 8 + g;
                bf[j][0] = Ks[st][cb][kk + t];
                bf[j][1] = Ks[st][cb][kk + t + 4];
            }
#pragma unroll
            for (int i = 0; i < 2; i++)
#pragma unroll
                for (int j = 0; j < 4; j++)
                    mma8(pacc[i][j], af[i], bf[j]);
        }

        // park next K into the other smem stage (double-buffered)
        if (nxt) {
#pragma unroll
            for (int i = 0; i < 4; i++) {
                int r = lr + i * 32;
                *(uint4*)&Ks[st ^ 1][r][lc] =
                    make_uint4(f2tf(kreg[i].x), f2tf(kreg[i].y), f2tf(kreg[i].z), f2tf(kreg[i].w));
            }
        }

        // ---- normalize, write attn (fp32, streaming), park tf32 P in smem ----
#pragma unroll
        for (int i = 0; i < 2; i++) {
            int rl = warp_m * 32 + i * 16 + g;
#pragma unroll
            for (int j = 0; j < 4; j++) {
                int cl = warp_n * 32 + j * 8 + 2 * t;
                float2 lo = make_float2(__expf(pacc[i][j][0] * 0.125f - rowM[i][0]) * rowI[i][0],
                                        __expf(pacc[i][j][1] * 0.125f - rowM[i][0]) * rowI[i][0]);
                float2 hi = make_float2(__expf(pacc[i][j][2] * 0.125f - rowM[i][1]) * rowI[i][1],
                                        __expf(pacc[i][j][3] * 0.125f - rowM[i][1]) * rowI[i][1]);
                __stcs((float2*)(Sb + (size_t)(m0 + rl) * L_SZ + it * 128 + cl), lo);
                __stcs((float2*)(Sb + (size_t)(m0 + rl + 8) * L_SZ + it * 128 + cl), hi);
                *(uint2*)&Ps[rl][cl]     = make_uint2(f2tf(lo.x), f2tf(lo.y));
                *(uint2*)&Ps[rl + 8][cl] = make_uint2(f2tf(hi.x), f2tf(hi.y));
            }
        }
        __syncthreads();   // Ps complete; Ks[st] fully consumed

        // ---- ctx += P @ V (from smem) ----
#pragma unroll
        for (int kk = 0; kk < 128; kk += 8) {
            unsigned af[2][4], bf[2][2];
#pragma unroll
            for (int i = 0; i < 2; i++) {
                int rb = warp_m * 32 + i * 16 + g;
                af[i][0] = Ps[rb][kk + t];
                af[i][1] = Ps[rb + 8][kk + t];
                af[i][2] = Ps[rb][kk + t + 4];
                af[i][3] = Ps[rb + 8][kk + t + 4];
            }
#pragma unroll
            for (int j = 0; j < 2; j++) {
                int cb = warp_n * 16 + j * 8 + g;
                bf[j][0] = Vs[kk + t][cb];
                bf[j][1] = Vs[kk + t + 4][cb];
            }
#pragma unroll
            for (int i = 0; i < 2; i++)
#pragma unroll
                for (int j = 0; j < 2; j++)
                    mma8(ctx[i][j], af[i], bf[j]);
        }
        __syncthreads();   // AV done -> Vs, Ps free

        // park next V (visible to all after next barrier, before next AV)
        if (nxt) {
#pragma unroll
            for (int i = 0; i < 4; i++) {
                int r = lr + i * 32;
                *(uint4*)&Vs[r][lc] =
                    make_uint4(f2tf(vreg[i].x), f2tf(vreg[i].y), f2tf(vreg[i].z), f2tf(vreg[i].w));
            }
        }
        st ^= 1;
    }

    // ---- write ctx in concat layout (B, L, D) ----
#pragma unroll
    for (int i = 0; i < 2; i++) {
#pragma unroll
        for (int j = 0; j < 2; j++) {
            int l = m0 + warp_m * 32 + i * 16 + g;
            int c = warp_n * 16 + j * 8 + 2 * t;
            float* d0 = g_ctx + ((size_t)b * L_SZ + l) * D_SZ + h * DH_SZ + c;
            float* d1 = g_ctx + ((size_t)b * L_SZ + l + 8) * D_SZ + h * DH_SZ + c;
            *(float2*)d0 = make_float2(ctx[i][j][0], ctx[i][j][1]);
            *(float2*)d1 = make_float2(ctx[i][j][2], ctx[i][j][3]);
        }
    }
}

// ============================================================================
extern "C" void kernel_launch(void* const* d_in, const int* in_sizes, int n_in,
                              void* d_out, int out_size)
{
    (void)in_sizes; (void)n_in;
    const float* x  = (const float*)d_in[0];
    const float* Wq = (const float*)d_in[1];
    const float* Wk = (const float*)d_in[2];
    const float* Wv = (const float*)d_in[3];
    const float* Wo = (const float*)d_in[4];
    float* out = (float*)d_out;

    const int fb = ((size_t)out_size < OUT_ELEMS + ATTN_ELEMS) ? 1 : 0;

    cudaFuncSetAttribute(proj_kernel,  cudaFuncAttributeMaxDynamicSharedMemorySize, PROJ_SMEM);
    cudaFuncSetAttribute(stats_kernel, cudaFuncAttributeMaxDynamicSharedMemorySize, STAT_SMEM);
    cudaFuncSetAttribute(attn_kernel,  cudaFuncAttributeMaxDynamicSharedMemorySize, ATTN_SMEM);

    // 1. fused QKV projections (grid.z selects Wq/Wk/Wv)
    proj_kernel<<<dim3(8, 32, 3), 512, PROJ_SMEM>>>(x, Wq, Wk, Wv, nullptr, -1);
    // 2. per-row softmax stats (M, 1/Z) via QK^T recompute
    stats_kernel<<<dim3(16, 32), 512, STAT_SMEM>>>();
    // 3. fused scores + normalize + attn-write + AV (ctx into g_ctx)
    attn_kernel<<<dim3(16, 32), 512, ATTN_SMEM>>>(out, fb);
    // 4. out-projection
    proj_kernel<<<dim3(8, 32, 1), 512, PROJ_SMEM>>>(nullptr, Wo, nullptr, nullptr, out, 3);
}

// round 17
// speedup vs baseline: 1.1025x; 1.1025x over previous
#include <cuda_runtime.h>
#include <cuda_bf16.h>

// Problem: B=2, L=2048, D=1024, H=16, DH=64
// Output buffer: [output (B,L,D) = 4,194,304 f32][attn (B,H,L,L) = 134,217,728 f32]

#define B_SZ   2
#define L_SZ   2048
#define D_SZ   1024
#define H_SZ   16
#define DH_SZ  64

static constexpr size_t OUT_ELEMS  = (size_t)B_SZ * L_SZ * D_SZ;        // 4194304
static constexpr size_t ATTN_ELEMS = (size_t)B_SZ * H_SZ * L_SZ * L_SZ; // 134217728
static constexpr size_t QKV_ELEMS  = (size_t)B_SZ * H_SZ * L_SZ * DH_SZ;// 4194304

// Scratch (allocation-free rule: __device__ globals)
__device__ __align__(16) float g_q[QKV_ELEMS];
__device__ __align__(16) float g_k[QKV_ELEMS];
__device__ __align__(16) float g_v[QKV_ELEMS];
__device__ __align__(16) float g_ctx[OUT_ELEMS];                      // ctx concat (B,L,D)
__device__ __align__(16) float2 g_stats[(size_t)B_SZ * H_SZ * L_SZ];  // {rowmax, 1/Z}
// Fallback attn scratch in case out_size only covers `output`
__device__ __align__(16) float g_attn_fb[ATTN_ELEMS];

__device__ __forceinline__ unsigned f2tf(float f) {
    unsigned u;
    asm("cvt.rna.tf32.f32 %0, %1;" : "=r"(u) : "f"(f));
    return u;
}

__device__ __forceinline__ void mma8(float c[4], const unsigned a[4], const unsigned b[2]) {
    asm volatile(
        "mma.sync.aligned.m16n8k8.row.col.f32.tf32.tf32.f32 "
        "{%0,%1,%2,%3}, {%4,%5,%6,%7}, {%8,%9}, {%0,%1,%2,%3};"
        : "+f"(c[0]), "+f"(c[1]), "+f"(c[2]), "+f"(c[3])
        : "r"(a[0]), "r"(a[1]), "r"(a[2]), "r"(a[3]), "r"(b[0]), "r"(b[1]));
}

__device__ __forceinline__ void cp16(void* smem_dst, const void* gmem_src) {
    unsigned d = (unsigned)__cvta_generic_to_shared(smem_dst);
    asm volatile("cp.async.cg.shared.global [%0], [%1], 16;" :: "r"(d), "l"(gmem_src));
}
__device__ __forceinline__ void cp_commit() {
    asm volatile("cp.async.commit_group;");
}

// merge two (max, sumexp) pairs
__device__ __forceinline__ void mz_merge(float& m, float& z, float om, float oz) {
    float mn = fmaxf(m, om);
    z = z * __expf(m - mn) + oz * __expf(om - mn);
    m = mn;
}

// ============================================================================
// NT GEMM: C[M=4096, N=1024] = A[4096,1024] * W[1024,1024]^T, TF32 mma.
// 512 threads, 16 warps (4m x 4n), warp tile 32x32, BM=BN=128, BK=32.
// 3-stage cp.async pipeline (fp32 in smem, tf32 cvt at fragment load) --
// no register staging, so __launch_bounds__(512, 2) fits WITHOUT spills.
// mode < 0: md = blockIdx.z in {0,1,2}: A = x, scatter into g_q/g_k/g_v (B,H,L,DH).
// mode == 3: A = g_ctx (concat), plain row-major write to dst.
// ============================================================================
static constexpr int PROJ_SMEM = (3 * 128 * 36 * 2) * 4;  // 110592 B (x2 CTAs = 221184)

__global__ void __launch_bounds__(512, 2) proj_kernel(
    const float* __restrict__ Ain, const float* __restrict__ W0,
    const float* __restrict__ W1, const float* __restrict__ W2,
    float* __restrict__ dst, int mode)
{
    extern __shared__ float shf[];
    float (*As)[128][36] = (float(*)[128][36])shf;
    float (*Ws)[128][36] = (float(*)[128][36])(shf + 3 * 128 * 36);

    const int md = (mode < 0) ? (int)blockIdx.z : mode;
    const float* W = (md == 1) ? W1 : (md == 2) ? W2 : W0;
    const float* A = (md == 3) ? (const float*)g_ctx : Ain;

    const int tid  = threadIdx.x;
    const int wid  = tid >> 5;
    const int lane = tid & 31;
    const int g = lane >> 2, t = lane & 3;
    const int warp_m = wid & 3, warp_n = wid >> 2;
    const int m0 = blockIdx.y * 128;
    const int n0 = blockIdx.x * 128;

    const int lr = tid >> 3;          // 0..63 (row within stage, +64 for i=1)
    const int lc = (tid & 7) << 2;    // 0..28

    float acc[2][4][4];
#pragma unroll
    for (int i = 0; i < 2; i++)
#pragma unroll
        for (int j = 0; j < 4; j++)
#pragma unroll
            for (int c = 0; c < 4; c++) acc[i][j][c] = 0.f;

    // prologue: issue stages 0 and 1
#pragma unroll
    for (int s = 0; s < 2; s++) {
#pragma unroll
        for (int i = 0; i < 2; i++) {
            int r = lr + i * 64;
            cp16(&As[s][r][lc], A + (size_t)(m0 + r) * 1024 + s * 32 + lc);
            cp16(&Ws[s][r][lc], W + (size_t)(n0 + r) * 1024 + s * 32 + lc);
        }
        cp_commit();
    }

    for (int it = 0; it < 32; it++) {
        const int st = it % 3;
        if (it < 31) asm volatile("cp.async.wait_group 1;" ::: "memory");
        else         asm volatile("cp.async.wait_group 0;" ::: "memory");
        __syncthreads();

#pragma unroll
        for (int kk = 0; kk < 32; kk += 8) {
            unsigned af[2][4], bf[4][2];
#pragma unroll
            for (int i = 0; i < 2; i++) {
                int rb = warp_m * 32 + i * 16 + g;
                af[i][0] = f2tf(As[st][rb][kk + t]);
                af[i][1] = f2tf(As[st][rb + 8][kk + t]);
                af[i][2] = f2tf(As[st][rb][kk + t + 4]);
                af[i][3] = f2tf(As[st][rb + 8][kk + t + 4]);
            }
#pragma unroll
            for (int j = 0; j < 4; j++) {
                int cb = warp_n * 32 + j * 8 + g;
                bf[j][0] = f2tf(Ws[st][cb][kk + t]);
                bf[j][1] = f2tf(Ws[st][cb][kk + t + 4]);
            }
#pragma unroll
            for (int i = 0; i < 2; i++)
#pragma unroll
                for (int j = 0; j < 4; j++)
                    mma8(acc[i][j], af[i], bf[j]);
        }

        // issue stage it+2 into (it+2)%3 — that stage was last read at iter it-1,
        // and the barrier above proved all threads left iter it-1. Safe.
        if (it + 2 < 32) {
            const int sn = (it + 2) % 3;
            const int k0 = (it + 2) * 32;
#pragma unroll
            for (int i = 0; i < 2; i++) {
                int r = lr + i * 64;
                cp16(&As[sn][r][lc], A + (size_t)(m0 + r) * 1024 + k0 + lc);
                cp16(&Ws[sn][r][lc], W + (size_t)(n0 + r) * 1024 + k0 + lc);
            }
            cp_commit();
        }
    }

    // Epilogue
#pragma unroll
    for (int i = 0; i < 2; i++) {
#pragma unroll
        for (int j = 0; j < 4; j++) {
            int r0 = m0 + warp_m * 32 + i * 16 + g;
            int c0 = n0 + warp_n * 32 + j * 8 + 2 * t;
            float2 lo = make_float2(acc[i][j][0], acc[i][j][1]);
            float2 hi = make_float2(acc[i][j][2], acc[i][j][3]);
            if (md == 3) {
                *(float2*)(dst + (size_t)r0 * 1024 + c0) = lo;
                *(float2*)(dst + (size_t)(r0 + 8) * 1024 + c0) = hi;
            } else {
                float* qkv = (md == 0) ? g_q : (md == 1) ? g_k : g_v;
                size_t i0 = ((size_t)((r0 >> 11) * H_SZ + (c0 >> 6)) * L_SZ + (r0 & 2047)) * DH_SZ + (c0 & 63);
                *(float2*)(qkv + i0) = lo;
                int r1 = r0 + 8;
                size_t i1 = ((size_t)((r1 >> 11) * H_SZ + (c0 >> 6)) * L_SZ + (r1 & 2047)) * DH_SZ + (c0 & 63);
                *(float2*)(qkv + i1) = hi;
            }
        }
    }
}

// ============================================================================
// Stats (flash pass-1): per (b,h, row-block 128), recompute S = Q K^T * 0.125
// streaming K in 128-col tiles; produce per-row (max M, 1/Z), Z = sum exp(s-M).
// cp.async: Q resident + 2-stage K ring (fp32 smem, cvt at fragment load).
// smem 108.5 KB, __launch_bounds__(512,2) -> 2 CTAs/SM, no staging regs.
// Values identical to the fused attn kernel (same cvt.rna, same mma order).
// ============================================================================
static constexpr int STAT_SMEM = (128 * 68 + 2 * 128 * 68 + 4 * 128 * 2) * 4; // 108544 B

__global__ void __launch_bounds__(512, 2) stats_kernel()
{
    extern __shared__ float shf[];
    float (*Qs)[68]      = (float(*)[68])shf;
    float (*Ks)[128][68] = (float(*)[128][68])(shf + 128 * 68);
    float (*red)[128][2] = (float(*)[128][2])(shf + 128 * 68 + 2 * 128 * 68);

    const int tid  = threadIdx.x;
    const int lane = tid & 31;
    const int wid  = tid >> 5;
    const int g = lane >> 2, t = lane & 3;
    const int warp_m = wid & 3, warp_n = wid >> 2;
    const int m0 = blockIdx.x * 128;
    const int bh = blockIdx.y;

    const float* Qb = g_q + (size_t)bh * L_SZ * DH_SZ;
    const float* Kb = g_k + (size_t)bh * L_SZ * DH_SZ;

    const int lr = tid >> 4;          // 0..31 (+32 per i), 16 float4 per 64-wide row
    const int lc = (tid & 15) << 2;

    // prologue: group0 = Q + K tile0, group1 = K tile1
#pragma unroll
    for (int i = 0; i < 4; i++) {
        int r = lr + i * 32;
        cp16(&Qs[r][lc], Qb + (size_t)(m0 + r) * DH_SZ + lc);
        cp16(&Ks[0][r][lc], Kb + (size_t)r * DH_SZ + lc);
    }
    cp_commit();
#pragma unroll
    for (int i = 0; i < 4; i++) {
        int r = lr + i * 32;
        cp16(&Ks[1][r][lc], Kb + (size_t)(128 + r) * DH_SZ + lc);
    }
    cp_commit();

    float m_[4] = {-1e30f, -1e30f, -1e30f, -1e30f};
    float z_[4] = {0.f, 0.f, 0.f, 0.f};

    for (int it = 0; it < 16; it++) {
        const int st = it & 1;
        if (it < 15) asm volatile("cp.async.wait_group 1;" ::: "memory");
        else         asm volatile("cp.async.wait_group 0;" ::: "memory");
        __syncthreads();

        float acc[2][4][4];
#pragma unroll
        for (int i = 0; i < 2; i++)
#pragma unroll
            for (int j = 0; j < 4; j++)
#pragma unroll
                for (int c = 0; c < 4; c++) acc[i][j][c] = 0.f;

#pragma unroll
        for (int kk = 0; kk < 64; kk += 8) {
            unsigned af[2][4], bf[4][2];
#pragma unroll
            for (int i = 0; i < 2; i++) {
                int rb = warp_m * 32 + i * 16 + g;
                af[i][0] = f2tf(Qs[rb][kk + t]);
                af[i][1] = f2tf(Qs[rb + 8][kk + t]);
                af[i][2] = f2tf(Qs[rb][kk + t + 4]);
                af[i][3] = f2tf(Qs[rb + 8][kk + t + 4]);
            }
#pragma unroll
            for (int j = 0; j < 4; j++) {
                int cb = warp_n * 32 + j * 8 + g;
                bf[j][0] = f2tf(Ks[st][cb][kk + t]);
                bf[j][1] = f2tf(Ks[st][cb][kk + t + 4]);
            }
#pragma unroll
            for (int i = 0; i < 2; i++)
#pragma unroll
                for (int j = 0; j < 4; j++)
                    mma8(acc[i][j], af[i], bf[j]);
        }

        // online (m,z) update (register-only)
#pragma unroll
        for (int i = 0; i < 2; i++) {
#pragma unroll
            for (int half = 0; half < 2; half++) {
                int ri = i * 2 + half;
                float v[8];
#pragma unroll
                for (int j = 0; j < 4; j++) {
                    v[2 * j]     = acc[i][j][half * 2]     * 0.125f;
                    v[2 * j + 1] = acc[i][j][half * 2 + 1] * 0.125f;
                }
                float tm = v[0];
#pragma unroll
                for (int k = 1; k < 8; k++) tm = fmaxf(tm, v[k]);
                float mn = fmaxf(m_[ri], tm);
                float zs = 0.f;
#pragma unroll
                for (int k = 0; k < 8; k++) zs += __expf(v[k] - mn);
                z_[ri] = z_[ri] * __expf(m_[ri] - mn) + zs;
                m_[ri] = mn;
            }
        }
        __syncthreads();   // all threads done reading Ks[st]

        if (it + 2 < 16) {
            const float* Kn = Kb + (size_t)(it + 2) * 128 * DH_SZ;
#pragma unroll
            for (int i = 0; i < 4; i++) {
                int r = lr + i * 32;
                cp16(&Ks[st][r][lc], Kn + (size_t)r * DH_SZ + lc);
            }
            cp_commit();
        }
    }

#pragma unroll
    for (int ri = 0; ri < 4; ri++) {
#pragma unroll
        for (int o = 1; o < 4; o <<= 1) {
            float om = __shfl_xor_sync(0xffffffffu, m_[ri], o);
            float oz = __shfl_xor_sync(0xffffffffu, z_[ri], o);
            mz_merge(m_[ri], z_[ri], om, oz);
        }
    }
    if (t == 0) {
#pragma unroll
        for (int i = 0; i < 2; i++) {
            int rl = warp_m * 32 + i * 16 + g;
            red[warp_n][rl][0]     = m_[i * 2];
            red[warp_n][rl][1]     = z_[i * 2];
            red[warp_n][rl + 8][0] = m_[i * 2 + 1];
            red[warp_n][rl + 8][1] = z_[i * 2 + 1];
        }
    }
    __syncthreads();
    if (tid < 128) {
        float M = red[0][tid][0], Z = red[0][tid][1];
#pragma unroll
        for (int w = 1; w < 4; w++) mz_merge(M, Z, red[w][tid][0], red[w][tid][1]);
        g_stats[(size_t)bh * L_SZ + m0 + tid] = make_float2(M, 1.0f / Z);
    }
}

// ============================================================================
// Fused attention: per (bh, 128-row Q block), loop over 16 K/V tiles of 128:
//   S = Q K^T * 0.125; P = exp(S - M) * invZ (stats precomputed);
//   write fp32 P to attn (streaming store, never re-read);
//   store tf32 P to smem; ctx += P @ V from smem.
// Q resident in smem all kernel. K double-buffered; V prefetched via regs.
// smem = 208896 B -> 1 CTA/SM, 16 warps.
// ============================================================================
static constexpr int ATTN_SMEM = (128 * 68 + 2 * 128 * 68 + 128 * 72 + 128 * 132) * 4; // 208896

__global__ void __launch_bounds__(512) attn_kernel(float* __restrict__ out, int fb)
{
    extern __shared__ unsigned sh[];
    unsigned (*Qs)[68]       = (unsigned(*)[68])sh;                         // 8704
    unsigned (*Ks)[128][68]  = (unsigned(*)[128][68])(sh + 8704);           // 17408
    unsigned (*Vs)[72]       = (unsigned(*)[72])(sh + 26112);               // 9216
    unsigned (*Ps)[132]      = (unsigned(*)[132])(sh + 35328);              // 16896

    float* attn = fb ? g_attn_fb : out + OUT_ELEMS;
    const int bh = blockIdx.y;
    const int m0 = blockIdx.x * 128;
    const int b  = bh >> 4;
    const int h  = bh & 15;

    const int tid  = threadIdx.x;
    const int lane = tid & 31;
    const int wid  = tid >> 5;
    const int g = lane >> 2, t = lane & 3;
    const int warp_m = wid & 3, warp_n = wid >> 2;

    const float* Qb = g_q + (size_t)bh * L_SZ * DH_SZ;
    const float* Kb = g_k + (size_t)bh * L_SZ * DH_SZ;
    const float* Vb = g_v + (size_t)bh * L_SZ * DH_SZ;
    float* Sb = attn + (size_t)bh * L_SZ * L_SZ;

    const int lr = tid >> 4;          // 0..31 (+32*i), 16 float4 per 64-wide row
    const int lc = (tid & 15) << 2;

    // per-thread softmax stats for the 4 rows this thread's fragments touch
    float rowM[2][2], rowI[2][2];
#pragma unroll
    for (int i = 0; i < 2; i++) {
        int rl = warp_m * 32 + i * 16 + g;
        float2 s0 = g_stats[(size_t)bh * L_SZ + m0 + rl];
        float2 s1 = g_stats[(size_t)bh * L_SZ + m0 + rl + 8];
        rowM[i][0] = s0.x; rowI[i][0] = s0.y;
        rowM[i][1] = s1.x; rowI[i][1] = s1.y;
    }

    // ctx accumulators: warp tile 32(m) x 16(dh)
    float ctx[2][2][4];
#pragma unroll
    for (int i = 0; i < 2; i++)
#pragma unroll
        for (int j = 0; j < 2; j++)
#pragma unroll
            for (int c = 0; c < 4; c++) ctx[i][j][c] = 0.f;

    // preload Q (resident), K tile 0, V tile 0
#pragma unroll
    for (int i = 0; i < 4; i++) {
        int r = lr + i * 32;
        float4 fq = *(const float4*)(Qb + (size_t)(m0 + r) * DH_SZ + lc);
        *(uint4*)&Qs[r][lc] = make_uint4(f2tf(fq.x), f2tf(fq.y), f2tf(fq.z), f2tf(fq.w));
        float4 fk = *(const float4*)(Kb + (size_t)r * DH_SZ + lc);
        *(uint4*)&Ks[0][r][lc] = make_uint4(f2tf(fk.x), f2tf(fk.y), f2tf(fk.z), f2tf(fk.w));
        float4 fv = *(const float4*)(Vb + (size_t)r * DH_SZ + lc);
        *(uint4*)&Vs[r][lc] = make_uint4(f2tf(fv.x), f2tf(fv.y), f2tf(fv.z), f2tf(fv.w));
    }
    __syncthreads();

    int st = 0;
    for (int it = 0; it < 16; it++) {
        const bool nxt = it < 15;
        // prefetch next K/V tiles into registers (hidden under S mma)
        float4 kreg[4], vreg[4];
        if (nxt) {
            const float* Kn = Kb + (size_t)(it + 1) * 128 * DH_SZ;
            const float* Vn = Vb + (size_t)(it + 1) * 128 * DH_SZ;
#pragma unroll
            for (int i = 0; i < 4; i++) {
                int r = lr + i * 32;
                kreg[i] = *(const float4*)(Kn + (size_t)r * DH_SZ + lc);
                vreg[i] = *(const float4*)(Vn + (size_t)r * DH_SZ + lc);
            }
        }

        // ---- S = Q K^T ----
        float pacc[2][4][4];
#pragma unroll
        for (int i = 0; i < 2; i++)
#pragma unroll
            for (int j = 0; j < 4; j++)
#pragma unroll
                for (int c = 0; c < 4; c++) pacc[i][j][c] = 0.f;

#pragma unroll
        for (int kk = 0; kk < 64; kk += 8) {
            unsigned af[2][4], bf[4][2];
#pragma unroll
            for (int i = 0; i < 2; i++) {
                int rb = warp_m * 32 + i * 16 + g;
                af[i][0] = Qs[rb][kk + t];
                af[i][1] = Qs[rb + 8][kk + t];
                af[i][2] = Qs[rb][kk + t + 4];
                af[i][3] = Qs[rb + 8][kk + t + 4];
            }
#pragma unroll
            for (int j = 0; j < 4; j++) {
                int cb = warp_n * 32 + j * 8 + g;
                bf[j][0] = Ks[st][cb][kk + t];
                bf[j][1] = Ks[st][cb][kk + t + 4];
            }
#pragma unroll
            for (int i = 0; i < 2; i++)
#pragma unroll
                for (int j = 0; j < 4; j++)
                    mma8(pacc[i][j], af[i], bf[j]);
        }

        // park next K into the other smem stage (double-buffered)
        if (nxt) {
#pragma unroll
            for (int i = 0; i < 4; i++) {
                int r = lr + i * 32;
                *(uint4*)&Ks[st ^ 1][r][lc] =
                    make_uint4(f2tf(kreg[i].x), f2tf(kreg[i].y), f2tf(kreg[i].z), f2tf(kreg[i].w));
            }
        }

        // ---- normalize, write attn (fp32, streaming), park tf32 P in smem ----
#pragma unroll
        for (int i = 0; i < 2; i++) {
            int rl = warp_m * 32 + i * 16 + g;
#pragma unroll
            for (int j = 0; j < 4; j++) {
                int cl = warp_n * 32 + j * 8 + 2 * t;
                float2 lo = make_float2(__expf(pacc[i][j][0] * 0.125f - rowM[i][0]) * rowI[i][0],
                                        __expf(pacc[i][j][1] * 0.125f - rowM[i][0]) * rowI[i][0]);
                float2 hi = make_float2(__expf(pacc[i][j][2] * 0.125f - rowM[i][1]) * rowI[i][1],
                                        __expf(pacc[i][j][3] * 0.125f - rowM[i][1]) * rowI[i][1]);
                __stcs((float2*)(Sb + (size_t)(m0 + rl) * L_SZ + it * 128 + cl), lo);
                __stcs((float2*)(Sb + (size_t)(m0 + rl + 8) * L_SZ + it * 128 + cl), hi);
                *(uint2*)&Ps[rl][cl]     = make_uint2(f2tf(lo.x), f2tf(lo.y));
                *(uint2*)&Ps[rl + 8][cl] = make_uint2(f2tf(hi.x), f2tf(hi.y));
            }
        }
        __syncthreads();   // Ps complete; Ks[st] fully consumed

        // ---- ctx += P @ V (from smem) ----
#pragma unroll
        for (int kk = 0; kk < 128; kk += 8) {
            unsigned af[2][4], bf[2][2];
#pragma unroll
            for (int i = 0; i < 2; i++) {
                int rb = warp_m * 32 + i * 16 + g;
                af[i][0] = Ps[rb][kk + t];
                af[i][1] = Ps[rb + 8][kk + t];
                af[i][2] = Ps[rb][kk + t + 4];
                af[i][3] = Ps[rb + 8][kk + t + 4];
            }
#pragma unroll
            for (int j = 0; j < 2; j++) {
                int cb = warp_n * 16 + j * 8 + g;
                bf[j][0] = Vs[kk + t][cb];
                bf[j][1] = Vs[kk + t + 4][cb];
            }
#pragma unroll
            for (int i = 0; i < 2; i++)
#pragma unroll
                for (int j = 0; j < 2; j++)
                    mma8(ctx[i][j], af[i], bf[j]);
        }
        __syncthreads();   // AV done -> Vs, Ps free

        // park next V (visible to all after next barrier, before next AV)
        if (nxt) {
#pragma unroll
            for (int i = 0; i < 4; i++) {
                int r = lr + i * 32;
                *(uint4*)&Vs[r][lc] =
                    make_uint4(f2tf(vreg[i].x), f2tf(vreg[i].y), f2tf(vreg[i].z), f2tf(vreg[i].w));
            }
        }
        st ^= 1;
    }

    // ---- write ctx in concat layout (B, L, D) ----
#pragma unroll
    for (int i = 0; i < 2; i++) {
#pragma unroll
        for (int j = 0; j < 2; j++) {
            int l = m0 + warp_m * 32 + i * 16 + g;
            int c = warp_n * 16 + j * 8 + 2 * t;
            float* d0 = g_ctx + ((size_t)b * L_SZ + l) * D_SZ + h * DH_SZ + c;
            float* d1 = g_ctx + ((size_t)b * L_SZ + l + 8) * D_SZ + h * DH_SZ + c;
            *(float2*)d0 = make_float2(ctx[i][j][0], ctx[i][j][1]);
            *(float2*)d1 = make_float2(ctx[i][j][2], ctx[i][j][3]);
        }
    }
}

// ============================================================================
extern "C" void kernel_launch(void* const* d_in, const int* in_sizes, int n_in,
                              void* d_out, int out_size)
{
    (void)in_sizes; (void)n_in;
    const float* x  = (const float*)d_in[0];
    const float* Wq = (const float*)d_in[1];
    const float* Wk = (const float*)d_in[2];
    const float* Wv = (const float*)d_in[3];
    const float* Wo = (const float*)d_in[4];
    float* out = (float*)d_out;

    const int fb = ((size_t)out_size < OUT_ELEMS + ATTN_ELEMS) ? 1 : 0;

    cudaFuncSetAttribute(proj_kernel,  cudaFuncAttributeMaxDynamicSharedMemorySize, PROJ_SMEM);
    cudaFuncSetAttribute(stats_kernel, cudaFuncAttributeMaxDynamicSharedMemorySize, STAT_SMEM);
    cudaFuncSetAttribute(attn_kernel,  cudaFuncAttributeMaxDynamicSharedMemorySize, ATTN_SMEM);

    // 1. fused QKV projections (grid.z selects Wq/Wk/Wv)
    proj_kernel<<<dim3(8, 32, 3), 512, PROJ_SMEM>>>(x, Wq, Wk, Wv, nullptr, -1);
    // 2. per-row softmax stats (M, 1/Z) via QK^T recompute
    stats_kernel<<<dim3(16, 32), 512, STAT_SMEM>>>();
    // 3. fused scores + normalize + attn-write + AV (ctx into g_ctx)
    attn_kernel<<<dim3(16, 32), 512, ATTN_SMEM>>>(out, fb);
    // 4. out-projection
    proj_kernel<<<dim3(8, 32, 1), 512, PROJ_SMEM>>>(nullptr, Wo, nullptr, nullptr, out, 3);
}